// round 1
// baseline (speedup 1.0000x reference)
#include <cuda_runtime.h>
#include <cstdint>

// Problem constants
#define BATCH   256
#define N0      4096   // layer1 in
#define N1      4096   // layer1 out / layer2 in
#define N2      4096   // layer2 out / layer3 in
#define N3      1024   // layer3 out

// Scratch routing tables (device globals — no allocation allowed)
__device__ int g_d1[N0];
__device__ int g_d2[N1];
__device__ int g_d3[N2];
__device__ int g_f [N0];   // composed routing: f[s] = d3[d2[d1[s]]]

// ---------------------------------------------------------------------------
// Row-wise argmax (first occurrence of max, matching jnp.argmax).
// One warp per row, float4 streaming loads. n_cols must be % 4 == 0.
// ---------------------------------------------------------------------------
__global__ void argmax_rows_kernel(const float* __restrict__ W,
                                   int n_rows, int n_cols,
                                   int* __restrict__ out_idx)
{
    const int warps_per_block = blockDim.x >> 5;
    const int row  = blockIdx.x * warps_per_block + (threadIdx.x >> 5);
    const int lane = threadIdx.x & 31;
    if (row >= n_rows) return;

    const float4* __restrict__ Wr =
        reinterpret_cast<const float4*>(W + (size_t)row * n_cols);
    const int n4 = n_cols >> 2;

    float best = -__int_as_float(0x7f800000);  // -inf
    int   bidx = 0;

    // Ascending index scan with strict '>' keeps the FIRST max.
    for (int i = lane; i < n4; i += 32) {
        float4 v = Wr[i];
        int base = i << 2;
        if (v.x > best) { best = v.x; bidx = base;     }
        if (v.y > best) { best = v.y; bidx = base + 1; }
        if (v.z > best) { best = v.z; bidx = base + 2; }
        if (v.w > best) { best = v.w; bidx = base + 3; }
    }

    // Warp reduction: larger value wins; tie -> smaller index (first occurrence).
    #pragma unroll
    for (int off = 16; off > 0; off >>= 1) {
        float ov = __shfl_down_sync(0xffffffffu, best, off);
        int   oi = __shfl_down_sync(0xffffffffu, bidx, off);
        if (ov > best || (ov == best && oi < bidx)) { best = ov; bidx = oi; }
    }
    if (lane == 0) out_idx[row] = bidx;
}

// ---------------------------------------------------------------------------
// Compose routing tables: f[s] = d3[d2[d1[s]]]
// ---------------------------------------------------------------------------
__global__ void compose_kernel()
{
    int s = blockIdx.x * blockDim.x + threadIdx.x;
    if (s < N0) {
        g_f[s] = g_d3[g_d2[g_d1[s]]];
    }
}

// ---------------------------------------------------------------------------
// Scatter: out[b, f[s]] += x[b, s], via shared-memory histogram per batch row.
// Counts are non-negative so all ReLUs are identities; empty bins stay 0.
// ---------------------------------------------------------------------------
__global__ void scatter_kernel(const int* __restrict__ x,
                               float* __restrict__ out)
{
    __shared__ int acc[N3];
    const int b = blockIdx.x;

    for (int i = threadIdx.x; i < N3; i += blockDim.x) acc[i] = 0;
    __syncthreads();

    const int* __restrict__ xb = x + (size_t)b * N0;
    // 4-wide vectorized count reads, smem atomics into 1024 bins.
    const int4* __restrict__ xb4 = reinterpret_cast<const int4*>(xb);
    for (int s4 = threadIdx.x; s4 < (N0 >> 2); s4 += blockDim.x) {
        int4 c = xb4[s4];
        int s = s4 << 2;
        if (c.x) atomicAdd(&acc[g_f[s]],     c.x);
        if (c.y) atomicAdd(&acc[g_f[s + 1]], c.y);
        if (c.z) atomicAdd(&acc[g_f[s + 2]], c.z);
        if (c.w) atomicAdd(&acc[g_f[s + 3]], c.w);
    }
    __syncthreads();

    float* __restrict__ ob = out + (size_t)b * N3;
    for (int i = threadIdx.x; i < N3; i += blockDim.x)
        ob[i] = (float)acc[i];
}

// ---------------------------------------------------------------------------
// Launch
//   d_in[0] = x  (int32,   [256, 4096])
//   d_in[1] = W1 (float32, [4096, 4096])
//   d_in[2] = W2 (float32, [4096, 4096])
//   d_in[3] = W3 (float32, [4096, 1024])
//   d_out   = float32 [256, 1024]
// ---------------------------------------------------------------------------
extern "C" void kernel_launch(void* const* d_in, const int* in_sizes, int n_in,
                              void* d_out, int out_size)
{
    const int*   x  = (const int*)  d_in[0];
    const float* W1 = (const float*)d_in[1];
    const float* W2 = (const float*)d_in[2];
    const float* W3 = (const float*)d_in[3];
    float* out = (float*)d_out;

    int* d1; cudaGetSymbolAddress((void**)&d1, g_d1);
    int* d2; cudaGetSymbolAddress((void**)&d2, g_d2);
    int* d3; cudaGetSymbolAddress((void**)&d3, g_d3);

    // 8 warps per block -> 8 rows per block
    const int TPB = 256;
    const int ROWS_PER_BLOCK = TPB / 32;

    argmax_rows_kernel<<<N0 / ROWS_PER_BLOCK, TPB>>>(W1, N0, N1, d1);
    argmax_rows_kernel<<<N1 / ROWS_PER_BLOCK, TPB>>>(W2, N1, N2, d2);
    argmax_rows_kernel<<<N2 / ROWS_PER_BLOCK, TPB>>>(W3, N2, N3, d3);

    compose_kernel<<<(N0 + 255) / 256, 256>>>();

    scatter_kernel<<<BATCH, 256>>>(x, out);
}

// round 2
// speedup vs baseline: 1.1836x; 1.1836x over previous
#include <cuda_runtime.h>
#include <cstdint>

// Problem constants
#define BATCH   256
#define N0      4096   // layer1 in
#define N1      4096   // layer1 out / layer2 in
#define N2      4096   // layer2 out / layer3 in
#define N3      1024   // layer3 out

#define ROWS_PER_BLOCK 8          // 8 warps/block, warp per row
#define NB_W1 (N0 / ROWS_PER_BLOCK)   // 512
#define NB_W2 (N1 / ROWS_PER_BLOCK)   // 512
#define NB_W3 (N2 / ROWS_PER_BLOCK)   // 512

// Scratch routing tables (device globals — allocation is forbidden)
__device__ int g_d1[N0];
__device__ int g_d2[N1];
__device__ int g_d3[N2];

// ---------------------------------------------------------------------------
// Row argmax, warp per row, 4x-unrolled float4 loads for MLP=4 per lane.
// First-occurrence semantics (jnp.argmax):
//  - within a 16-element group: ascending-index select chain on equality
//  - across groups (ascending i): strict '>' keeps earlier group
//  - across lanes: reduction tie-breaks to smaller index
// n_cols must be a multiple of 512 (4096 and 1024 both are).
// ---------------------------------------------------------------------------
__device__ __forceinline__ void argmax_row(const float* __restrict__ W,
                                           int row, int n_cols, int lane,
                                           int* __restrict__ out_idx)
{
    const float4* __restrict__ Wr =
        reinterpret_cast<const float4*>(W + (size_t)row * n_cols);
    const int n4 = n_cols >> 2;

    float best = -__int_as_float(0x7f800000);  // -inf
    int   bidx = 0;

    for (int i = lane; i < n4; i += 128) {
        // 4 independent loads in flight
        float4 a = Wr[i];
        float4 b = Wr[i + 32];
        float4 c = Wr[i + 64];
        float4 d = Wr[i + 96];

        float ma = fmaxf(fmaxf(a.x, a.y), fmaxf(a.z, a.w));
        float mb = fmaxf(fmaxf(b.x, b.y), fmaxf(b.z, b.w));
        float mc = fmaxf(fmaxf(c.x, c.y), fmaxf(c.z, c.w));
        float md = fmaxf(fmaxf(d.x, d.y), fmaxf(d.z, d.w));
        float g  = fmaxf(fmaxf(ma, mb), fmaxf(mc, md));

        if (g > best) {
            best = g;
            // resolve first index of g within the group, ascending order
            int ia = i << 2;          // elements ia..ia+3      (a)
            int ib = (i + 32) << 2;   // b
            int ic = (i + 64) << 2;   // c
            int id = (i + 96) << 2;   // d
            bidx =
                (a.x == g) ? ia     :
                (a.y == g) ? ia + 1 :
                (a.z == g) ? ia + 2 :
                (a.w == g) ? ia + 3 :
                (b.x == g) ? ib     :
                (b.y == g) ? ib + 1 :
                (b.z == g) ? ib + 2 :
                (b.w == g) ? ib + 3 :
                (c.x == g) ? ic     :
                (c.y == g) ? ic + 1 :
                (c.z == g) ? ic + 2 :
                (c.w == g) ? ic + 3 :
                (d.x == g) ? id     :
                (d.y == g) ? id + 1 :
                (d.z == g) ? id + 2 :
                             id + 3;
        }
    }

    // warp reduction: larger value wins; tie -> smaller index
    #pragma unroll
    for (int off = 16; off > 0; off >>= 1) {
        float ov = __shfl_down_sync(0xffffffffu, best, off);
        int   oi = __shfl_down_sync(0xffffffffu, bidx, off);
        if (ov > best || (ov == best && oi < bidx)) { best = ov; bidx = oi; }
    }
    if (lane == 0) out_idx[row] = bidx;
}

// ---------------------------------------------------------------------------
// One launch computes all three routing tables.
// blocks [0,512)    -> W1 rows (4096 cols)
// blocks [512,1024) -> W2 rows (4096 cols)
// blocks [1024,1536)-> W3 rows (1024 cols)
// ---------------------------------------------------------------------------
__global__ void __launch_bounds__(256) fused_argmax_kernel(
    const float* __restrict__ W1,
    const float* __restrict__ W2,
    const float* __restrict__ W3)
{
    const int warp = threadIdx.x >> 5;
    const int lane = threadIdx.x & 31;
    const int bid  = blockIdx.x;

    if (bid < NB_W1) {
        int row = bid * ROWS_PER_BLOCK + warp;
        argmax_row(W1, row, N1, lane, g_d1);
    } else if (bid < NB_W1 + NB_W2) {
        int row = (bid - NB_W1) * ROWS_PER_BLOCK + warp;
        argmax_row(W2, row, N2, lane, g_d2);
    } else {
        int row = (bid - NB_W1 - NB_W2) * ROWS_PER_BLOCK + warp;
        argmax_row(W3, row, N3, lane, g_d3);
    }
}

// ---------------------------------------------------------------------------
// Scatter with inline compose: out[b, d3[d2[d1[s]]]] += x[b, s].
// Shared-memory histogram per batch row; counts >= 0 so ReLUs are identity.
// Routing tables (48KB total) stay L2-hot across all 256 blocks.
// ---------------------------------------------------------------------------
__global__ void __launch_bounds__(256) scatter_kernel(
    const int* __restrict__ x,
    float* __restrict__ out)
{
    __shared__ int acc[N3];
    const int b = blockIdx.x;

    for (int i = threadIdx.x; i < N3; i += blockDim.x) acc[i] = 0;
    __syncthreads();

    const int4* __restrict__ xb4 =
        reinterpret_cast<const int4*>(x + (size_t)b * N0);

    #pragma unroll
    for (int it = 0; it < (N0 >> 2) / 256; ++it) {
        int s4 = it * 256 + threadIdx.x;
        int4 c = xb4[s4];
        int s = s4 << 2;
        // compose on the fly; 4 independent 3-deep L2-hit chains
        int f0 = g_d3[g_d2[g_d1[s]]];
        int f1 = g_d3[g_d2[g_d1[s + 1]]];
        int f2 = g_d3[g_d2[g_d1[s + 2]]];
        int f3 = g_d3[g_d2[g_d1[s + 3]]];
        if (c.x) atomicAdd(&acc[f0], c.x);
        if (c.y) atomicAdd(&acc[f1], c.y);
        if (c.z) atomicAdd(&acc[f2], c.z);
        if (c.w) atomicAdd(&acc[f3], c.w);
    }
    __syncthreads();

    float* __restrict__ ob = out + (size_t)b * N3;
    for (int i = threadIdx.x; i < N3; i += blockDim.x)
        ob[i] = (float)acc[i];
}

// ---------------------------------------------------------------------------
// Launch
//   d_in[0] = x  (int32,   [256, 4096])
//   d_in[1] = W1 (float32, [4096, 4096])
//   d_in[2] = W2 (float32, [4096, 4096])
//   d_in[3] = W3 (float32, [4096, 1024])
//   d_out   = float32 [256, 1024]
// ---------------------------------------------------------------------------
extern "C" void kernel_launch(void* const* d_in, const int* in_sizes, int n_in,
                              void* d_out, int out_size)
{
    const int*   x  = (const int*)  d_in[0];
    const float* W1 = (const float*)d_in[1];
    const float* W2 = (const float*)d_in[2];
    const float* W3 = (const float*)d_in[3];
    float* out = (float*)d_out;

    fused_argmax_kernel<<<NB_W1 + NB_W2 + NB_W3, 256>>>(W1, W2, W3);
    scatter_kernel<<<BATCH, 256>>>(x, out);
}

// round 3
// speedup vs baseline: 1.3091x; 1.1061x over previous
#include <cuda_runtime.h>
#include <cstdint>

// Problem constants
#define BATCH   256
#define N0      4096   // layer1 in
#define N1      4096   // layer1 out / layer2 in
#define N2      4096   // layer2 out / layer3 in
#define N3      1024   // layer3 out

#define ROWS_PER_BLOCK 8              // 8 warps/block, warp per row
#define NB_W1 (N0 / ROWS_PER_BLOCK)   // 512
#define NB_W2 (N1 / ROWS_PER_BLOCK)   // 512
#define NB_W3 (N2 / ROWS_PER_BLOCK)   // 512

// Routing tables as u16 (all indices < 4096). 16-byte aligned for uint4 loads.
__device__ __align__(16) unsigned short g_d1[N0];
__device__ __align__(16) unsigned short g_d2[N1];
__device__ __align__(16) unsigned short g_d3[N2];

// ---------------------------------------------------------------------------
// Row argmax, warp per row, 8x-unrolled float4 loads (MLP=8 per lane).
// First-occurrence semantics (jnp.argmax):
//  - resolve chain scans candidates in DESCENDING index order so the final
//    (surviving) write is the smallest index equal to the group max
//  - across iterations (ascending i): strict '>' keeps the earlier group
//  - across lanes: reduction tie-breaks to smaller index
// Requires n_cols % 1024 == 0 (4096 ✓, 1024 ✓).
// ---------------------------------------------------------------------------
__device__ __forceinline__ void argmax_row(const float* __restrict__ W,
                                           int row, int n_cols, int lane,
                                           unsigned short* __restrict__ out_idx)
{
    const float4* __restrict__ Wr =
        reinterpret_cast<const float4*>(W + (size_t)row * n_cols);
    const int n4 = n_cols >> 2;

    float best = -__int_as_float(0x7f800000);  // -inf
    int   bidx = 0;

    for (int i = lane; i < n4; i += 256) {
        float4 v[8];
        #pragma unroll
        for (int u = 0; u < 8; ++u) v[u] = Wr[i + u * 32];   // 8 loads in flight

        float g = -__int_as_float(0x7f800000);
        #pragma unroll
        for (int u = 0; u < 8; ++u) {
            float m = fmaxf(fmaxf(v[u].x, v[u].y), fmaxf(v[u].z, v[u].w));
            g = fmaxf(g, m);
        }

        if (g > best) {
            best = g;
            int idx = 0;
            // descending scan: last surviving assignment = smallest index
            #pragma unroll
            for (int u = 7; u >= 0; --u) {
                int base = (i + u * 32) << 2;
                if (v[u].w == g) idx = base + 3;
                if (v[u].z == g) idx = base + 2;
                if (v[u].y == g) idx = base + 1;
                if (v[u].x == g) idx = base;
            }
            bidx = idx;
        }
    }

    // warp reduction: larger value wins; tie -> smaller index
    #pragma unroll
    for (int off = 16; off > 0; off >>= 1) {
        float ov = __shfl_down_sync(0xffffffffu, best, off);
        int   oi = __shfl_down_sync(0xffffffffu, bidx, off);
        if (ov > best || (ov == best && oi < bidx)) { best = ov; bidx = oi; }
    }
    if (lane == 0) out_idx[row] = (unsigned short)bidx;
}

// ---------------------------------------------------------------------------
// One launch computes all three routing tables.
// ---------------------------------------------------------------------------
__global__ void __launch_bounds__(256) fused_argmax_kernel(
    const float* __restrict__ W1,
    const float* __restrict__ W2,
    const float* __restrict__ W3)
{
    const int warp = threadIdx.x >> 5;
    const int lane = threadIdx.x & 31;
    const int bid  = blockIdx.x;

    if (bid < NB_W1) {
        int row = bid * ROWS_PER_BLOCK + warp;
        argmax_row(W1, row, N1, lane, g_d1);
    } else if (bid < NB_W1 + NB_W2) {
        int row = (bid - NB_W1) * ROWS_PER_BLOCK + warp;
        argmax_row(W2, row, N2, lane, g_d2);
    } else {
        int row = (bid - NB_W1 - NB_W2) * ROWS_PER_BLOCK + warp;
        argmax_row(W3, row, N3, lane, g_d3);
    }
}

// ---------------------------------------------------------------------------
// Scatter with smem-staged routing tables:
//   out[b, t3[t2[t1[s]]]] += x[b, s]
// Tables (u16, 24KB) + histogram (4KB) live in shared memory, so the compose
// chains are 3 LDS hops with 8 independent chains per thread — latency-free.
// Counts >= 0 so all ReLUs are identity; every output bin is written.
// ---------------------------------------------------------------------------
__global__ void __launch_bounds__(512) scatter_kernel(
    const int* __restrict__ x,
    float* __restrict__ out)
{
    __shared__ unsigned short t1[N0];
    __shared__ unsigned short t2[N1];
    __shared__ unsigned short t3[N2];
    __shared__ int hist[N3];

    const int tid = threadIdx.x;
    const int b   = blockIdx.x;

    // Cooperative table load: 4096 u16 = 512 uint4 per table; 512 threads -> 1 each.
    {
        const uint4* __restrict__ s1 = reinterpret_cast<const uint4*>(g_d1);
        const uint4* __restrict__ s2 = reinterpret_cast<const uint4*>(g_d2);
        const uint4* __restrict__ s3 = reinterpret_cast<const uint4*>(g_d3);
        reinterpret_cast<uint4*>(t1)[tid] = s1[tid];
        reinterpret_cast<uint4*>(t2)[tid] = s2[tid];
        reinterpret_cast<uint4*>(t3)[tid] = s3[tid];
    }
    hist[tid]       = 0;
    hist[tid + 512] = 0;
    __syncthreads();

    const int4* __restrict__ xb4 =
        reinterpret_cast<const int4*>(x + (size_t)b * N0);

    // 8 elements per thread: two coalesced int4 loads, 8 independent 3-LDS chains.
    int4 ca = xb4[tid];
    int4 cb = xb4[tid + 512];
    const int sa = tid << 2;
    const int sb = sa + (N0 >> 1);

    int a0 = t1[sa],     a1 = t1[sa + 1], a2 = t1[sa + 2], a3 = t1[sa + 3];
    int b0 = t1[sb],     b1 = t1[sb + 1], b2 = t1[sb + 2], b3 = t1[sb + 3];

    a0 = t2[a0]; a1 = t2[a1]; a2 = t2[a2]; a3 = t2[a3];
    b0 = t2[b0]; b1 = t2[b1]; b2 = t2[b2]; b3 = t2[b3];

    a0 = t3[a0]; a1 = t3[a1]; a2 = t3[a2]; a3 = t3[a3];
    b0 = t3[b0]; b1 = t3[b1]; b2 = t3[b2]; b3 = t3[b3];

    if (ca.x) atomicAdd(&hist[a0], ca.x);
    if (ca.y) atomicAdd(&hist[a1], ca.y);
    if (ca.z) atomicAdd(&hist[a2], ca.z);
    if (ca.w) atomicAdd(&hist[a3], ca.w);
    if (cb.x) atomicAdd(&hist[b0], cb.x);
    if (cb.y) atomicAdd(&hist[b1], cb.y);
    if (cb.z) atomicAdd(&hist[b2], cb.z);
    if (cb.w) atomicAdd(&hist[b3], cb.w);

    __syncthreads();

    float* __restrict__ ob = out + (size_t)b * N3;
    ob[tid]       = (float)hist[tid];
    ob[tid + 512] = (float)hist[tid + 512];
}

// ---------------------------------------------------------------------------
// Launch
//   d_in[0] = x  (int32,   [256, 4096])
//   d_in[1] = W1 (float32, [4096, 4096])
//   d_in[2] = W2 (float32, [4096, 4096])
//   d_in[3] = W3 (float32, [4096, 1024])
//   d_out   = float32 [256, 1024]
// ---------------------------------------------------------------------------
extern "C" void kernel_launch(void* const* d_in, const int* in_sizes, int n_in,
                              void* d_out, int out_size)
{
    const int*   x  = (const int*)  d_in[0];
    const float* W1 = (const float*)d_in[1];
    const float* W2 = (const float*)d_in[2];
    const float* W3 = (const float*)d_in[3];
    float* out = (float*)d_out;

    fused_argmax_kernel<<<NB_W1 + NB_W2 + NB_W3, 256>>>(W1, W2, W3);
    scatter_kernel<<<BATCH, 512>>>(x, out);
}